// round 3
// baseline (speedup 1.0000x reference)
#include <cuda_runtime.h>
#include <cuda_bf16.h>
#include <math.h>

// Problem dims
#define B_   64
#define T_   256
#define U_   1024
#define G3   3072
#define M_   (B_ * T_)

// Recurrent persistent-kernel config
#define GRID_R   128        // CTAs; CTA owns 8 j-values (24 output cols), full K
#define THR_R    256        // 8 warps; warp owns k-slice of 128
#define BST      1032       // smem stride (halves) for resident Ut rows
#define HRS      24         // smem stride (halves) for h chunk rows (16 + 8 pad)

// Big-GEMM config
#define AST      40         // smem row stride (halves) for 32-k chunks

// -------- device scratch --------------------------------------------------
__device__ float          g_xp [(size_t)M_ * G3];
__device__ unsigned short g_xhi[(size_t)M_ * U_];
__device__ unsigned short g_xlo[(size_t)M_ * U_];
__device__ unsigned short g_y1hi[(size_t)M_ * U_];
__device__ unsigned short g_y1lo[(size_t)M_ * U_];
__device__ unsigned short g_wthi[(size_t)G3 * U_];
__device__ unsigned short g_wtlo[(size_t)G3 * U_];
__device__ unsigned short g_uthi[(size_t)G3 * U_];
__device__ unsigned short g_utlo[(size_t)G3 * U_];
__device__ float          g_h  [B_ * U_];
__device__ unsigned short g_hhi[B_ * U_];
__device__ unsigned short g_hlo[B_ * U_];
__device__ unsigned g_grp[8];
__device__ unsigned g_root;
__device__ unsigned g_gen;

// -------- helpers ---------------------------------------------------------
__device__ __forceinline__ void split2(float v, unsigned short& hi, unsigned short& lo) {
    __nv_bfloat16 h = __float2bfloat16(v);
    float r = v - __bfloat162float(h);
    __nv_bfloat16 l = __float2bfloat16(r);
    hi = *(unsigned short*)&h;
    lo = *(unsigned short*)&l;
}

__device__ __forceinline__ void ldsm4(unsigned (&r)[4], const void* p) {
    unsigned a = (unsigned)__cvta_generic_to_shared(p);
    asm volatile("ldmatrix.sync.aligned.m8n8.x4.shared.b16 {%0,%1,%2,%3}, [%4];"
                 : "=r"(r[0]), "=r"(r[1]), "=r"(r[2]), "=r"(r[3]) : "r"(a));
}

__device__ __forceinline__ void ldsm2(unsigned (&r)[2], const void* p) {
    unsigned a = (unsigned)__cvta_generic_to_shared(p);
    asm volatile("ldmatrix.sync.aligned.m8n8.x2.shared.b16 {%0,%1}, [%2];"
                 : "=r"(r[0]), "=r"(r[1]) : "r"(a));
}

__device__ __forceinline__ void mma16816(float (&c)[4],
    unsigned a0, unsigned a1, unsigned a2, unsigned a3, unsigned b0, unsigned b1) {
    asm volatile(
        "mma.sync.aligned.m16n8k16.row.col.f32.bf16.bf16.f32 "
        "{%0,%1,%2,%3}, {%4,%5,%6,%7}, {%8,%9}, {%0,%1,%2,%3};"
        : "+f"(c[0]), "+f"(c[1]), "+f"(c[2]), "+f"(c[3])
        : "r"(a0), "r"(a1), "r"(a2), "r"(a3), "r"(b0), "r"(b1));
}

__device__ __forceinline__ void cp16(void* smem_dst, const void* gsrc) {
    unsigned d = (unsigned)__cvta_generic_to_shared(smem_dst);
    asm volatile("cp.async.cg.shared.global [%0], [%1], 16;" :: "r"(d), "l"(gsrc));
}

// Generic warp MMA tile (used by big GEMM, unchanged from R2)
template<int MSUB, int NSUB, int ASTR, int BSTR>
__device__ __forceinline__ void mma_tile(
    const unsigned short* As, const unsigned short* Bs,
    int mb, int nb, int kbase,
    int a_ro, int a_ko, int b_ro, int b_ko,
    float acc[][NSUB][4])
{
    unsigned aF[MSUB][4], bF[NSUB / 2][4];
    #pragma unroll
    for (int i = 0; i < MSUB; i++)
        ldsm4(aF[i], &As[(mb + i * 16 + a_ro) * ASTR + kbase + a_ko]);
    #pragma unroll
    for (int p = 0; p < NSUB / 2; p++)
        ldsm4(bF[p], &Bs[(nb + p * 16 + b_ro) * BSTR + kbase + b_ko]);
    #pragma unroll
    for (int i = 0; i < MSUB; i++)
        #pragma unroll
        for (int j = 0; j < NSUB; j++) {
            int p = j >> 1, q = (j & 1) << 1;
            mma16816(acc[i][j], aF[i][0], aF[i][1], aF[i][2], aF[i][3],
                     bF[p][q], bF[p][q + 1]);
        }
}

// -------- hierarchical monotonic grid barrier ------------------------------
__device__ __forceinline__ void grid_sync(int bid) {
    __syncthreads();
    if (threadIdx.x == 0) {
        __threadfence();
        unsigned gen = *(volatile unsigned*)&g_gen;
        if ((atomicAdd(&g_grp[bid & 7], 1u) & 15u) == 15u) {
            if ((atomicAdd(&g_root, 1u) & 7u) == 7u)
                atomicAdd(&g_gen, 1u);
        }
        while (*(volatile unsigned*)&g_gen == gen) { }
        __threadfence();
    }
    __syncthreads();
}

// ---------------------------------------------------------------------------
// Split x (fp32) -> bf16 hi/lo
// ---------------------------------------------------------------------------
__global__ void split_x_kernel(const float* __restrict__ x) {
    size_t n4 = (size_t)M_ * U_ / 4;
    for (size_t i = (size_t)blockIdx.x * blockDim.x + threadIdx.x; i < n4;
         i += (size_t)gridDim.x * blockDim.x) {
        float4 v = ((const float4*)x)[i];
        unsigned short h0, h1, h2, h3, l0, l1, l2, l3;
        split2(v.x, h0, l0); split2(v.y, h1, l1);
        split2(v.z, h2, l2); split2(v.w, h3, l3);
        ((ushort4*)g_xhi)[i] = make_ushort4(h0, h1, h2, h3);
        ((ushort4*)g_xlo)[i] = make_ushort4(l0, l1, l2, l3);
    }
}

// ---------------------------------------------------------------------------
// Transpose + split: M[1024,3072] fp32 -> dest[3072,1024] bf16 hi/lo
// ---------------------------------------------------------------------------
__global__ void transpose_split_kernel(const float* __restrict__ Min, int dest) {
    __shared__ float tile[32][33];
    unsigned short* dh = dest ? g_uthi : g_wthi;
    unsigned short* dl = dest ? g_utlo : g_wtlo;
    int bx = blockIdx.x, by = blockIdx.y, tx = threadIdx.x;
    int x = bx * 32 + tx;
    int y0 = by * 32;
    #pragma unroll
    for (int r = threadIdx.y; r < 32; r += 8)
        tile[r][tx] = Min[(size_t)(y0 + r) * G3 + x];
    __syncthreads();
    int xo = by * 32 + tx;
    int yo0 = bx * 32;
    #pragma unroll
    for (int r = threadIdx.y; r < 32; r += 8) {
        unsigned short hi, lo;
        split2(tile[tx][r], hi, lo);
        dh[(size_t)(yo0 + r) * U_ + xo] = hi;
        dl[(size_t)(yo0 + r) * U_ + xo] = lo;
    }
}

// ---------------------------------------------------------------------------
// Big GEMM (tensor core, split-bf16 x3)  — unchanged from R2
// ---------------------------------------------------------------------------
__global__ __launch_bounds__(256) void gemm_mma_kernel(
    const float* __restrict__ bias, int a_sel)
{
    const unsigned short* Ahg = a_sel ? g_y1hi : g_xhi;
    const unsigned short* Alg = a_sel ? g_y1lo : g_xlo;
    __shared__ __align__(16) unsigned short Ah[128 * AST], Al[128 * AST];
    __shared__ __align__(16) unsigned short Bh[128 * AST], Bl[128 * AST];

    const int tid = threadIdx.x, w = tid >> 5, l = tid & 31;
    const int row0 = blockIdx.y * 128, col0 = blockIdx.x * 128;
    const int mb = (w >> 2) * 64, nb = (w & 3) * 32;

    const int asel = l >> 3;
    const int a_ro = ((asel & 1) << 3) + (l & 7);
    const int a_ko = (asel >> 1) << 3;
    const int b_ro = ((asel >> 1) << 3) + (l & 7);
    const int b_ko = (asel & 1) << 3;

    const int s0 = tid, s1 = tid + 256;
    const int r0 = s0 >> 2, k0s = (s0 & 3) << 3;
    const int r1 = s1 >> 2, k1s = (s1 & 3) << 3;

    float acc[4][4][4];
    #pragma unroll
    for (int i = 0; i < 4; i++)
        #pragma unroll
        for (int j = 0; j < 4; j++)
            #pragma unroll
            for (int c = 0; c < 4; c++) acc[i][j][c] = 0.f;

    for (int k0 = 0; k0 < U_; k0 += 32) {
        uint4 vah0 = *(const uint4*)&Ahg[(size_t)(row0 + r0) * U_ + k0 + k0s];
        uint4 vah1 = *(const uint4*)&Ahg[(size_t)(row0 + r1) * U_ + k0 + k1s];
        uint4 val0 = *(const uint4*)&Alg[(size_t)(row0 + r0) * U_ + k0 + k0s];
        uint4 val1 = *(const uint4*)&Alg[(size_t)(row0 + r1) * U_ + k0 + k1s];
        uint4 vbh0 = *(const uint4*)&g_wthi[(size_t)(col0 + r0) * U_ + k0 + k0s];
        uint4 vbh1 = *(const uint4*)&g_wthi[(size_t)(col0 + r1) * U_ + k0 + k1s];
        uint4 vbl0 = *(const uint4*)&g_wtlo[(size_t)(col0 + r0) * U_ + k0 + k0s];
        uint4 vbl1 = *(const uint4*)&g_wtlo[(size_t)(col0 + r1) * U_ + k0 + k1s];
        __syncthreads();
        *(uint4*)&Ah[r0 * AST + k0s] = vah0;
        *(uint4*)&Ah[r1 * AST + k1s] = vah1;
        *(uint4*)&Al[r0 * AST + k0s] = val0;
        *(uint4*)&Al[r1 * AST + k1s] = val1;
        *(uint4*)&Bh[r0 * AST + k0s] = vbh0;
        *(uint4*)&Bh[r1 * AST + k1s] = vbh1;
        *(uint4*)&Bl[r0 * AST + k0s] = vbl0;
        *(uint4*)&Bl[r1 * AST + k1s] = vbl1;
        __syncthreads();
        #pragma unroll
        for (int kk = 0; kk < 2; kk++) {
            mma_tile<4, 4, AST, AST>(Ah, Bh, mb, nb, kk * 16, a_ro, a_ko, b_ro, b_ko, acc);
            mma_tile<4, 4, AST, AST>(Ah, Bl, mb, nb, kk * 16, a_ro, a_ko, b_ro, b_ko, acc);
            mma_tile<4, 4, AST, AST>(Al, Bh, mb, nb, kk * 16, a_ro, a_ko, b_ro, b_ko, acc);
        }
    }

    #pragma unroll
    for (int i = 0; i < 4; i++)
        #pragma unroll
        for (int j = 0; j < 4; j++) {
            int r = row0 + mb + i * 16 + (l >> 2);
            int c = col0 + nb + j * 8 + ((l & 3) << 1);
            float bz0 = bias[c], bz1 = bias[c + 1];
            *(float2*)&g_xp[(size_t)r * G3 + c] =
                make_float2(acc[i][j][0] + bz0, acc[i][j][1] + bz1);
            *(float2*)&g_xp[(size_t)(r + 8) * G3 + c] =
                make_float2(acc[i][j][2] + bz0, acc[i][j][3] + bz1);
        }
}

// ---------------------------------------------------------------------------
// Persistent GRU recurrence, merged design:
// CTA owns 8 j-values (24 cols across 3 gates), full K=1024 split over 8 warps.
// Per step: per-warp cp.async-pipelined h chunks -> 36 HMMA x 8 chunks ->
// smem reduction over warps -> gate math -> ONE grid barrier.
// smem: Ut hi/lo resident (24x1032 halves each) + per-warp h staging (dbuf).
// ---------------------------------------------------------------------------
#define US_CNT   (24 * BST)                  // halves per Ut precision
#define HS_WARP  6144                        // halves per warp staging region
#define SMEM_DYN ((2 * US_CNT + 8 * HS_WARP) * 2)   // 197376 bytes

__global__ __launch_bounds__(THR_R, 1) void gru_recurrent_kernel(
    const float* __restrict__ bias_r,
    const float* __restrict__ h0,
    float* __restrict__ y_ext,
    int y_internal,
    float* __restrict__ state_out)
{
    extern __shared__ __align__(16) unsigned short sm[];
    unsigned short* us_hi = sm;
    unsigned short* us_lo = sm + US_CNT;
    unsigned short* hs    = sm + 2 * US_CNT;

    const int tid = threadIdx.x, bid = blockIdx.x;
    const int w = tid >> 5, l = tid & 31;
    const int j0 = bid * 8;
    const int kw = w * 128;
    unsigned short* hw = hs + w * HS_WARP;

    // init hidden state (+ splits)
    for (int i = bid * THR_R + tid; i < B_ * U_; i += GRID_R * THR_R) {
        float v = h0 ? h0[i] : 0.f;
        g_h[i] = v;
        unsigned short hi, lo;
        split2(v, hi, lo);
        g_hhi[i] = hi;
        g_hlo[i] = lo;
    }

    // load resident Ut slice: smem row s (0..23) -> Ut row (s>>3)*1024 + j0 + (s&7)
    for (int idx = tid; idx < 24 * 128; idx += THR_R) {
        int row = idx >> 7, q = idx & 127;
        int utrow = (row >> 3) * U_ + j0 + (row & 7);
        *(uint4*)&us_hi[row * BST + q * 8] = *(const uint4*)&g_uthi[(size_t)utrow * U_ + q * 8];
        *(uint4*)&us_lo[row * BST + q * 8] = *(const uint4*)&g_utlo[(size_t)utrow * U_ + q * 8];
    }
    grid_sync(bid);

    // fragment index precompute
    const int asel = l >> 3;
    const int a_ro = ((asel & 1) << 3) + (l & 7);
    const int a_ko = (asel >> 1) << 3;
    const int b_ro = ((asel >> 1) << 3) + (l & 7);
    const int b_ko = (asel & 1) << 3;
    const int b2row = 16 + (l & 7);
    const int b2ko  = ((l >> 3) & 1) << 3;

    // t-invariant bias for this thread's two gate outputs
    float bz[2], br[2], bh[2];
    int ob[2], oc[2];
    #pragma unroll
    for (int q = 0; q < 2; q++) {
        int o = tid + q * 256;
        ob[q] = o >> 3;
        oc[q] = o & 7;
        int j = j0 + oc[q];
        bz[q] = bias_r[j];
        br[q] = bias_r[U_ + j];
        bh[q] = bias_r[2 * U_ + j];
    }

    for (int t = 0; t < T_; t++) {
        float acc[4][3][4];
        #pragma unroll
        for (int i = 0; i < 4; i++)
            #pragma unroll
            for (int j = 0; j < 3; j++)
                #pragma unroll
                for (int c = 0; c < 4; c++) acc[i][j][c] = 0.f;

        // prologue: stage chunk 0 into buf 0
        {
            int k = kw;
            unsigned short* dh = hw;
            unsigned short* dl = hw + 1536;
            #pragma unroll
            for (int q = 0; q < 4; q++) {
                int s = l + q * 32;
                int row = s >> 1, off = (s & 1) * 8;
                cp16(&dh[row * HRS + off], &g_hhi[row * U_ + k + off]);
                cp16(&dl[row * HRS + off], &g_hlo[row * U_ + k + off]);
            }
            asm volatile("cp.async.commit_group;");
        }

        #pragma unroll
        for (int c = 0; c < 8; c++) {
            if (c < 7) {
                int k = kw + (c + 1) * 16;
                unsigned short* dh = hw + ((c + 1) & 1) * 3072;
                unsigned short* dl = dh + 1536;
                #pragma unroll
                for (int q = 0; q < 4; q++) {
                    int s = l + q * 32;
                    int row = s >> 1, off = (s & 1) * 8;
                    cp16(&dh[row * HRS + off], &g_hhi[row * U_ + k + off]);
                    cp16(&dl[row * HRS + off], &g_hlo[row * U_ + k + off]);
                }
                asm volatile("cp.async.commit_group;");
                asm volatile("cp.async.wait_group 1;");
            } else {
                asm volatile("cp.async.wait_group 0;");
            }
            __syncwarp();

            unsigned short* ah = hw + (c & 1) * 3072;
            unsigned short* al = ah + 1536;
            int kb = kw + c * 16;

            unsigned aH[4][4], aL[4][4], bH4[4], bL4[4], bH2[2], bL2[2];
            #pragma unroll
            for (int i = 0; i < 4; i++)
                ldsm4(aH[i], &ah[(i * 16 + a_ro) * HRS + a_ko]);
            #pragma unroll
            for (int i = 0; i < 4; i++)
                ldsm4(aL[i], &al[(i * 16 + a_ro) * HRS + a_ko]);
            ldsm4(bH4, &us_hi[b_ro * BST + kb + b_ko]);
            ldsm2(bH2, &us_hi[b2row * BST + kb + b2ko]);
            ldsm4(bL4, &us_lo[b_ro * BST + kb + b_ko]);
            ldsm2(bL2, &us_lo[b2row * BST + kb + b2ko]);

            #pragma unroll
            for (int i = 0; i < 4; i++) {
                mma16816(acc[i][0], aH[i][0], aH[i][1], aH[i][2], aH[i][3], bH4[0], bH4[1]);
                mma16816(acc[i][1], aH[i][0], aH[i][1], aH[i][2], aH[i][3], bH4[2], bH4[3]);
                mma16816(acc[i][2], aH[i][0], aH[i][1], aH[i][2], aH[i][3], bH2[0], bH2[1]);
                mma16816(acc[i][0], aH[i][0], aH[i][1], aH[i][2], aH[i][3], bL4[0], bL4[1]);
                mma16816(acc[i][1], aH[i][0], aH[i][1], aH[i][2], aH[i][3], bL4[2], bL4[3]);
                mma16816(acc[i][2], aH[i][0], aH[i][1], aH[i][2], aH[i][3], bL2[0], bL2[1]);
                mma16816(acc[i][0], aL[i][0], aL[i][1], aL[i][2], aL[i][3], bH4[0], bH4[1]);
                mma16816(acc[i][1], aL[i][0], aL[i][1], aL[i][2], aL[i][3], bH4[2], bH4[3]);
                mma16816(acc[i][2], aL[i][0], aL[i][1], aL[i][2], aL[i][3], bH2[0], bH2[1]);
            }
        }
        __syncwarp();

        // write per-warp partials into own staging region (fp32 view, 6144B)
        float* red_w = (float*)hw;
        #pragma unroll
        for (int i = 0; i < 4; i++) {
            int r = i * 16 + (l >> 2);
            int cc = (l & 3) << 1;
            #pragma unroll
            for (int j = 0; j < 3; j++) {
                *(float2*)&red_w[r * 24 + j * 8 + cc] =
                    make_float2(acc[i][j][0], acc[i][j][1]);
                *(float2*)&red_w[(r + 8) * 24 + j * 8 + cc] =
                    make_float2(acc[i][j][2], acc[i][j][3]);
            }
        }
        __syncthreads();

        // reduce over 8 warps + gates + h update (2 outputs per thread)
        #pragma unroll
        for (int q = 0; q < 2; q++) {
            int b = ob[q], cc = oc[q];
            float rz = bz[q], rr = br[q], rh = bh[q];
            #pragma unroll
            for (int w2 = 0; w2 < 8; w2++) {
                const float* rw = (const float*)(hs + w2 * HS_WARP);
                rz += rw[b * 24 + cc];
                rr += rw[b * 24 + 8 + cc];
                rh += rw[b * 24 + 16 + cc];
            }
            int j = j0 + cc;
            const float* xr = &g_xp[(size_t)(b * T_ + t) * G3];
            float xz = xr[j];
            float xrr = xr[U_ + j];
            float xh = xr[2 * U_ + j];
            float z = 1.f / (1.f + expf(-(xz + rz)));
            float r = 1.f / (1.f + expf(-(xrr + rr)));
            float hh = tanhf(xh + r * rh);
            int e = b * U_ + j;
            float hnew = z * g_h[e] + (1.f - z) * hh;
            g_h[e] = hnew;
            unsigned short hi, lo;
            split2(hnew, hi, lo);
            g_hhi[e] = hi;
            g_hlo[e] = lo;
            size_t yi = (size_t)(b * T_ + t) * U_ + j;
            if (y_internal) {
                g_y1hi[yi] = hi;
                g_y1lo[yi] = lo;
            } else {
                y_ext[yi] = hnew;
            }
        }
        grid_sync(bid);
    }

    if (state_out)
        for (int i = bid * THR_R + tid; i < B_ * U_; i += GRID_R * THR_R)
            state_out[i] = __ldcg(&g_h[i]);
}

// ---------------------------------------------------------------------------
extern "C" void kernel_launch(void* const* d_in, const int* in_sizes, int n_in,
                              void* d_out, int out_size) {
    (void)in_sizes; (void)n_in; (void)out_size;
    const float* x      = (const float*)d_in[0];
    const float* hidden = (const float*)d_in[1];
    const float* W1     = (const float*)d_in[2];
    const float* U1     = (const float*)d_in[3];
    const float* b1     = (const float*)d_in[4];
    const float* W2     = (const float*)d_in[5];
    const float* U2     = (const float*)d_in[6];
    const float* b2     = (const float*)d_in[7];
    float* out   = (float*)d_out;
    float* state = out + (size_t)M_ * U_;

    cudaFuncSetAttribute(gru_recurrent_kernel,
                         cudaFuncAttributeMaxDynamicSharedMemorySize, SMEM_DYN);

    dim3 tB(32, 8), tG(96, 32);
    dim3 gG(G3 / 128, M_ / 128);

    // ---- Layer 1 ----
    split_x_kernel<<<2048, 256>>>(x);
    transpose_split_kernel<<<tG, tB>>>(W1, 0);
    transpose_split_kernel<<<tG, tB>>>(U1, 1);
    gemm_mma_kernel<<<gG, 256>>>(b1, 0);
    gru_recurrent_kernel<<<GRID_R, THR_R, SMEM_DYN>>>(b1 + G3, hidden,
                                                      nullptr, 1, nullptr);
    // ---- Layer 2 ----
    transpose_split_kernel<<<tG, tB>>>(W2, 0);
    transpose_split_kernel<<<tG, tB>>>(U2, 1);
    gemm_mma_kernel<<<gG, 256>>>(b2, 1);
    gru_recurrent_kernel<<<GRID_R, THR_R, SMEM_DYN>>>(b2 + G3, nullptr,
                                                      out, 0, state);
}

// round 5
// speedup vs baseline: 1.0525x; 1.0525x over previous
#include <cuda_runtime.h>
#include <cuda_bf16.h>
#include <math.h>

// Problem dims
#define B_   64
#define T_   256
#define U_   1024
#define G3   3072
#define M_   (B_ * T_)

// Recurrent persistent-kernel config (R2 structure)
#define GRID_R   128
#define THR_R    256
#define KSPLIT   8          // K=1024 -> 8 slices of 128
#define NSPLIT   16         // N=3072 -> 16 slices of 192
#define NCOLS    192
#define KTILE    128
#define UST      136        // smem row stride (halves)

// Big-GEMM config: CTA 128x256, BK=32, 8 warps (2m x 4n), warp tile 64x64
#define GA_ST    40         // smem row stride (halves): 32 + 8 pad
#define G_STG    30720      // halves per pipeline stage (A hi/lo + B hi/lo)

// -------- device scratch --------------------------------------------------
__device__ float          g_xp [(size_t)M_ * G3];
__device__ unsigned short g_xhi[(size_t)M_ * U_];
__device__ unsigned short g_xlo[(size_t)M_ * U_];
__device__ unsigned short g_y1hi[(size_t)M_ * U_];
__device__ unsigned short g_y1lo[(size_t)M_ * U_];
__device__ unsigned short g_wthi[(size_t)G3 * U_];
__device__ unsigned short g_wtlo[(size_t)G3 * U_];
__device__ unsigned short g_uthi[(size_t)G3 * U_];
__device__ unsigned short g_utlo[(size_t)G3 * U_];
__device__ float          g_rp [(size_t)KSPLIT * B_ * G3];
__device__ float          g_h  [B_ * U_];
__device__ unsigned short g_hhi[B_ * U_];
__device__ unsigned short g_hlo[B_ * U_];
__device__ unsigned g_grp[8];
__device__ unsigned g_root;
__device__ unsigned g_gen;

// -------- helpers ---------------------------------------------------------
__device__ __forceinline__ void split2(float v, unsigned short& hi, unsigned short& lo) {
    __nv_bfloat16 h = __float2bfloat16(v);
    float r = v - __bfloat162float(h);
    __nv_bfloat16 l = __float2bfloat16(r);
    hi = *(unsigned short*)&h;
    lo = *(unsigned short*)&l;
}

__device__ __forceinline__ void ldsm4(unsigned (&r)[4], const void* p) {
    unsigned a = (unsigned)__cvta_generic_to_shared(p);
    asm volatile("ldmatrix.sync.aligned.m8n8.x4.shared.b16 {%0,%1,%2,%3}, [%4];"
                 : "=r"(r[0]), "=r"(r[1]), "=r"(r[2]), "=r"(r[3]) : "r"(a));
}

__device__ __forceinline__ void mma16816(float (&c)[4],
    const unsigned (&a)[4], unsigned b0, unsigned b1) {
    asm volatile(
        "mma.sync.aligned.m16n8k16.row.col.f32.bf16.bf16.f32 "
        "{%0,%1,%2,%3}, {%4,%5,%6,%7}, {%8,%9}, {%0,%1,%2,%3};"
        : "+f"(c[0]), "+f"(c[1]), "+f"(c[2]), "+f"(c[3])
        : "r"(a[0]), "r"(a[1]), "r"(a[2]), "r"(a[3]), "r"(b0), "r"(b1));
}

__device__ __forceinline__ void cp16(void* smem_dst, const void* gsrc) {
    unsigned d = (unsigned)__cvta_generic_to_shared(smem_dst);
    asm volatile("cp.async.cg.shared.global [%0], [%1], 16;" :: "r"(d), "l"(gsrc));
}

// -------- hierarchical monotonic grid barrier (validated in R3) ------------
__device__ __forceinline__ void grid_sync(int bid) {
    __syncthreads();
    if (threadIdx.x == 0) {
        __threadfence();
        unsigned gen = *(volatile unsigned*)&g_gen;
        if ((atomicAdd(&g_grp[bid & 7], 1u) & 15u) == 15u) {
            if ((atomicAdd(&g_root, 1u) & 7u) == 7u)
                atomicAdd(&g_gen, 1u);
        }
        while (*(volatile unsigned*)&g_gen == gen) { __nanosleep(32); }
        __threadfence();
    }
    __syncthreads();
}

// ---------------------------------------------------------------------------
__global__ void split_x_kernel(const float* __restrict__ x) {
    size_t n4 = (size_t)M_ * U_ / 4;
    for (size_t i = (size_t)blockIdx.x * blockDim.x + threadIdx.x; i < n4;
         i += (size_t)gridDim.x * blockDim.x) {
        float4 v = ((const float4*)x)[i];
        unsigned short h0, h1, h2, h3, l0, l1, l2, l3;
        split2(v.x, h0, l0); split2(v.y, h1, l1);
        split2(v.z, h2, l2); split2(v.w, h3, l3);
        ((ushort4*)g_xhi)[i] = make_ushort4(h0, h1, h2, h3);
        ((ushort4*)g_xlo)[i] = make_ushort4(l0, l1, l2, l3);
    }
}

__global__ void transpose_split_kernel(const float* __restrict__ Min, int dest) {
    __shared__ float tile[32][33];
    unsigned short* dh = dest ? g_uthi : g_wthi;
    unsigned short* dl = dest ? g_utlo : g_wtlo;
    int bx = blockIdx.x, by = blockIdx.y, tx = threadIdx.x;
    int x = bx * 32 + tx;
    int y0 = by * 32;
    #pragma unroll
    for (int r = threadIdx.y; r < 32; r += 8)
        tile[r][tx] = Min[(size_t)(y0 + r) * G3 + x];
    __syncthreads();
    int xo = by * 32 + tx;
    int yo0 = bx * 32;
    #pragma unroll
    for (int r = threadIdx.y; r < 32; r += 8) {
        unsigned short hi, lo;
        split2(tile[tx][r], hi, lo);
        dh[(size_t)(yo0 + r) * U_ + xo] = hi;
        dl[(size_t)(yo0 + r) * U_ + xo] = lo;
    }
}

// ---------------------------------------------------------------------------
// Big GEMM: C[M_,G3] = A@W + bias. CTA 128x256, BK=32, double-buffered cp.async.
// 8 warps as 2m x 4n; warp tile 64x64. Split-bf16 x3 passes.
// smem stage layout (halves): Ah[128*40] | Al[128*40] | Bh[256*40] | Bl[256*40]
// ---------------------------------------------------------------------------
#define GEMM_SMEM (2 * G_STG * 2)   // 122880 bytes

__global__ __launch_bounds__(256) void gemm_mma_kernel(
    const float* __restrict__ bias, int a_sel)
{
    const unsigned short* Ahg = a_sel ? g_y1hi : g_xhi;
    const unsigned short* Alg = a_sel ? g_y1lo : g_xlo;
    extern __shared__ __align__(16) unsigned short sm[];

    const int tid = threadIdx.x, w = tid >> 5, l = tid & 31;
    const int row0 = blockIdx.y * 128, col0 = blockIdx.x * 256;
    const int mb = (w >> 2) * 64, nb = (w & 3) * 64;

    const int asel = l >> 3;
    const int a_ro = ((asel & 1) << 3) + (l & 7);
    const int a_ko = (asel >> 1) << 3;
    const int b_ro = ((asel >> 1) << 3) + (l & 7);
    const int b_ko = (asel & 1) << 3;

    float acc[4][8][4];
    #pragma unroll
    for (int i = 0; i < 4; i++)
        #pragma unroll
        for (int j = 0; j < 8; j++)
            #pragma unroll
            for (int c = 0; c < 4; c++) acc[i][j][c] = 0.f;

    // staging: 12 x 16B per thread per stage (A:4 segs of 256, B:8 segs of 256)
    auto stage = [&](int iter) {
        int k0 = iter * 32;
        unsigned short* sb = sm + (iter & 1) * G_STG;
        #pragma unroll
        for (int q = 0; q < 4; q++) {            // A hi/lo
            int seg = q * 256 + tid;             // 0..1023
            int prec = seg >> 9;                 // 0 hi, 1 lo
            int r = (seg >> 2) & 127, off = (seg & 3) << 3;
            const unsigned short* src = prec ? Alg : Ahg;
            cp16(&sb[prec * 5120 + r * GA_ST + off],
                 &src[(size_t)(row0 + r) * U_ + k0 + off]);
        }
        #pragma unroll
        for (int q = 0; q < 8; q++) {            // B hi/lo
            int seg = q * 256 + tid;             // 0..2047
            int prec = seg >> 10;
            int r = (seg >> 2) & 255, off = (seg & 3) << 3;
            const unsigned short* src = prec ? g_wtlo : g_wthi;
            cp16(&sb[10240 + prec * 10240 + r * GA_ST + off],
                 &src[(size_t)(col0 + r) * U_ + k0 + off]);
        }
        asm volatile("cp.async.commit_group;");
    };

    stage(0);
    for (int iter = 0; iter < 32; iter++) {
        if (iter < 31) {
            stage(iter + 1);
            asm volatile("cp.async.wait_group 1;");
        } else {
            asm volatile("cp.async.wait_group 0;");
        }
        __syncthreads();
        unsigned short* sb = sm + (iter & 1) * G_STG;
        unsigned short* Ah = sb;
        unsigned short* Al = sb + 5120;
        unsigned short* Bh = sb + 10240;
        unsigned short* Bl = sb + 20480;
        #pragma unroll
        for (int kk = 0; kk < 2; kk++) {
            int kb = kk * 16;
            unsigned aH[4][4], aL[4][4];
            #pragma unroll
            for (int i = 0; i < 4; i++) {
                ldsm4(aH[i], &Ah[(mb + i * 16 + a_ro) * GA_ST + kb + a_ko]);
                ldsm4(aL[i], &Al[(mb + i * 16 + a_ro) * GA_ST + kb + a_ko]);
            }
            #pragma unroll
            for (int p = 0; p < 4; p++) {
                // consume each B fragment immediately to cap live registers
                {
                    unsigned bH[4];
                    ldsm4(bH, &Bh[(nb + p * 16 + b_ro) * GA_ST + kb + b_ko]);
                    #pragma unroll
                    for (int i = 0; i < 4; i++) {
                        mma16816(acc[i][2 * p],     aH[i], bH[0], bH[1]);
                        mma16816(acc[i][2 * p + 1], aH[i], bH[2], bH[3]);
                    }
                    #pragma unroll
                    for (int i = 0; i < 4; i++) {
                        mma16816(acc[i][2 * p],     aL[i], bH[0], bH[1]);
                        mma16816(acc[i][2 * p + 1], aL[i], bH[2], bH[3]);
                    }
                }
                {
                    unsigned bL[4];
                    ldsm4(bL, &Bl[(nb + p * 16 + b_ro) * GA_ST + kb + b_ko]);
                    #pragma unroll
                    for (int i = 0; i < 4; i++) {
                        mma16816(acc[i][2 * p],     aH[i], bL[0], bL[1]);
                        mma16816(acc[i][2 * p + 1], aH[i], bL[2], bL[3]);
                    }
                }
            }
        }
        __syncthreads();
    }

    #pragma unroll
    for (int i = 0; i < 4; i++)
        #pragma unroll
        for (int j = 0; j < 8; j++) {
            int r = row0 + mb + i * 16 + (l >> 2);
            int c = col0 + nb + j * 8 + ((l & 3) << 1);
            float bz0 = bias[c], bz1 = bias[c + 1];
            *(float2*)&g_xp[(size_t)r * G3 + c] =
                make_float2(acc[i][j][0] + bz0, acc[i][j][1] + bz1);
            *(float2*)&g_xp[(size_t)(r + 8) * G3 + c] =
                make_float2(acc[i][j][2] + bz0, acc[i][j][3] + bz1);
        }
}

// ---------------------------------------------------------------------------
// Persistent GRU recurrence: R2 split-K structure + fast barrier + one-shot
// cp.async h staging. CTA (ks,ns): rp[64, 192] partial over K slice of 128.
// ---------------------------------------------------------------------------
#define US_CNT   (NCOLS * UST)
#define HS_CNT   (64 * UST)
#define SMEM_DYN ((2 * US_CNT + 2 * HS_CNT) * 2)   // 139264 bytes

__global__ __launch_bounds__(THR_R, 1) void gru_recurrent_kernel(
    const float* __restrict__ bias_r,
    const float* __restrict__ h0,
    float* __restrict__ y_ext,
    int y_internal,
    float* __restrict__ state_out)
{
    extern __shared__ __align__(16) unsigned short sm[];
    unsigned short* us_hi = sm;
    unsigned short* us_lo = sm + US_CNT;
    unsigned short* hs_hi = sm + 2 * US_CNT;
    unsigned short* hs_lo = hs_hi + HS_CNT;

    const int tid = threadIdx.x, bid = blockIdx.x;
    const int w = tid >> 5, l = tid & 31;
    const int ks = bid >> 4;      // 0..7
    const int ns = bid & 15;      // 0..15

    // init hidden state (+ splits)
    for (int i = bid * THR_R + tid; i < B_ * U_; i += GRID_R * THR_R) {
        float v = h0 ? h0[i] : 0.f;
        g_h[i] = v;
        unsigned short hi, lo;
        split2(v, hi, lo);
        g_hhi[i] = hi;
        g_hlo[i] = lo;
    }

    // preload resident Ut slice: NCOLS rows x KTILE halves (hi & lo)
    for (int s = tid; s < NCOLS * (KTILE / 8); s += THR_R) {
        int row = s >> 4, k8 = (s & 15) << 3;
        size_t g = (size_t)(ns * NCOLS + row) * U_ + ks * KTILE + k8;
        *(uint4*)&us_hi[row * UST + k8] = *(const uint4*)&g_uthi[g];
        *(uint4*)&us_lo[row * UST + k8] = *(const uint4*)&g_utlo[g];
    }
    grid_sync(bid);

    const int asel = l >> 3;
    const int a_ro = ((asel & 1) << 3) + (l & 7);
    const int a_ko = (asel >> 1) << 3;
    const int b_ro = ((asel >> 1) << 3) + (l & 7);
    const int b_ko = (asel & 1) << 3;
    const int mb = (w >> 2) * 32;   // warp grid 2m x 4n, warp tile 32x48
    const int nb = (w & 3) * 48;

    // t-invariant phase-B per-thread constants
    float bz[2], br2[2], bh2[2];
    int ob[2], oj[2];
    #pragma unroll
    for (int q = 0; q < 2; q++) {
        int e = bid * THR_R + tid + q * GRID_R * THR_R;
        ob[q] = e >> 10;
        oj[q] = e & 1023;
        bz[q]  = bias_r[oj[q]];
        br2[q] = bias_r[U_ + oj[q]];
        bh2[q] = bias_r[2 * U_ + oj[q]];
    }

    for (int t = 0; t < T_; t++) {
        // ---- one-shot stage of h slice: 64 rows x 128 halves, hi+lo ----
        #pragma unroll
        for (int q = 0; q < 8; q++) {
            int seg = q * 256 + tid;          // 0..2047
            int prec = seg >> 10;
            int s = seg & 1023;
            int row = s >> 4, off = (s & 15) << 3;
            unsigned short* dst = prec ? hs_lo : hs_hi;
            const unsigned short* src = prec ? g_hlo : g_hhi;
            cp16(&dst[row * UST + off], &src[row * U_ + ks * KTILE + off]);
        }
        asm volatile("cp.async.commit_group;");
        asm volatile("cp.async.wait_group 0;");
        __syncthreads();

        // ---- Phase A: 36 MMAs x 8 k16 ----
        float acc[2][6][4];
        #pragma unroll
        for (int i = 0; i < 2; i++)
            #pragma unroll
            for (int j = 0; j < 6; j++)
                #pragma unroll
                for (int c = 0; c < 4; c++) acc[i][j][c] = 0.f;

        #pragma unroll
        for (int k16 = 0; k16 < 8; k16++) {
            int kb = k16 * 16;
            unsigned aH[2][4], aL[2][4], bH[3][4], bL[3][4];
            #pragma unroll
            for (int i = 0; i < 2; i++) {
                ldsm4(aH[i], &hs_hi[(mb + i * 16 + a_ro) * UST + kb + a_ko]);
                ldsm4(aL[i], &hs_lo[(mb + i * 16 + a_ro) * UST + kb + a_ko]);
            }
            #pragma unroll
            for (int p = 0; p < 3; p++) {
                ldsm4(bH[p], &us_hi[(nb + p * 16 + b_ro) * UST + kb + b_ko]);
                ldsm4(bL[p], &us_lo[(nb + p * 16 + b_ro) * UST + kb + b_ko]);
            }
            #pragma unroll
            for (int i = 0; i < 2; i++)
                #pragma unroll
                for (int p = 0; p < 3; p++) {
                    mma16816(acc[i][2 * p],     aH[i], bH[p][0], bH[p][1]);
                    mma16816(acc[i][2 * p + 1], aH[i], bH[p][2], bH[p][3]);
                    mma16816(acc[i][2 * p],     aH[i], bL[p][0], bL[p][1]);
                    mma16816(acc[i][2 * p + 1], aH[i], bL[p][2], bL[p][3]);
                    mma16816(acc[i][2 * p],     aL[i], bH[p][0], bH[p][1]);
                    mma16816(acc[i][2 * p + 1], aL[i], bH[p][2], bH[p][3]);
                }
        }

        // ---- store partials ----
        {
            size_t base = (size_t)ks * B_ * G3;
            #pragma unroll
            for (int i = 0; i < 2; i++)
                #pragma unroll
                for (int j = 0; j < 6; j++) {
                    int r = mb + i * 16 + (l >> 2);
                    int c = ns * NCOLS + nb + j * 8 + ((l & 3) << 1);
                    *(float2*)&g_rp[base + (size_t)r * G3 + c] =
                        make_float2(acc[i][j][0], acc[i][j][1]);
                    *(float2*)&g_rp[base + (size_t)(r + 8) * G3 + c] =
                        make_float2(acc[i][j][2], acc[i][j][3]);
                }
        }
        grid_sync(bid);

        // ---- Phase B: reduce partials, gates, h update ----
        #pragma unroll
        for (int q = 0; q < 2; q++) {
            int b = ob[q], j = oj[q];
            float rz = bz[q], rr = br2[q], rh = bh2[q];
            size_t rb = (size_t)b * G3 + j;
            #pragma unroll
            for (int p = 0; p < KSPLIT; p++) {
                size_t off = (size_t)p * B_ * G3 + rb;
                rz += __ldcg(&g_rp[off]);
                rr += __ldcg(&g_rp[off + U_]);
                rh += __ldcg(&g_rp[off + 2 * U_]);
            }
            const float* xr = &g_xp[(size_t)(b * T_ + t) * G3];
            float xz = xr[j];
            float xrr = xr[U_ + j];
            float xh = xr[2 * U_ + j];
            float z = 1.f / (1.f + expf(-(xz + rz)));
            float r = 1.f / (1.f + expf(-(xrr + rr)));
            float hh = tanhf(xh + r * rh);
            int e = b * U_ + j;
            float hnew = z * g_h[e] + (1.f - z) * hh;
            g_h[e] = hnew;
            unsigned short hi, lo;
            split2(hnew, hi, lo);
            g_hhi[e] = hi;
            g_hlo[e] = lo;
            size_t yi = (size_t)(b * T_ + t) * U_ + j;
            if (y_internal) {
                g_y1hi[yi] = hi;
                g_y1lo[yi] = lo;
            } else {
                y_ext[yi] = hnew;
            }
        }
        grid_sync(bid);
    }

    if (state_out)
        for (int i = bid * THR_R + tid; i < B_ * U_; i += GRID_R * THR_R)
            state_out[i] = __ldcg(&g_h[i]);
}

// ---------------------------------------------------------------------------
extern "C" void kernel_launch(void* const* d_in, const int* in_sizes, int n_in,
                              void* d_out, int out_size) {
    (void)in_sizes; (void)n_in; (void)out_size;
    const float* x      = (const float*)d_in[0];
    const float* hidden = (const float*)d_in[1];
    const float* W1     = (const float*)d_in[2];
    const float* U1     = (const float*)d_in[3];
    const float* b1     = (const float*)d_in[4];
    const float* W2     = (const float*)d_in[5];
    const float* U2     = (const float*)d_in[6];
    const float* b2     = (const float*)d_in[7];
    float* out   = (float*)d_out;
    float* state = out + (size_t)M_ * U_;

    cudaFuncSetAttribute(gru_recurrent_kernel,
                         cudaFuncAttributeMaxDynamicSharedMemorySize, SMEM_DYN);
    cudaFuncSetAttribute(gemm_mma_kernel,
                         cudaFuncAttributeMaxDynamicSharedMemorySize, GEMM_SMEM);

    dim3 tB(32, 8), tG(96, 32);
    dim3 gG(G3 / 256, M_ / 128);

    // ---- Layer 1 ----
    split_x_kernel<<<2048, 256>>>(x);
    transpose_split_kernel<<<tG, tB>>>(W1, 0);
    transpose_split_kernel<<<tG, tB>>>(U1, 1);
    gemm_mma_kernel<<<gG, 256, GEMM_SMEM>>>(b1, 0);
    gru_recurrent_kernel<<<GRID_R, THR_R, SMEM_DYN>>>(b1 + G3, hidden,
                                                      nullptr, 1, nullptr);
    // ---- Layer 2 ----
    transpose_split_kernel<<<tG, tB>>>(W2, 0);
    transpose_split_kernel<<<tG, tB>>>(U2, 1);
    gemm_mma_kernel<<<gG, 256, GEMM_SMEM>>>(b2, 1);
    gru_recurrent_kernel<<<GRID_R, THR_R, SMEM_DYN>>>(b2 + G3, nullptr,
                                                      out, 0, state);
}

// round 8
// speedup vs baseline: 1.0898x; 1.0355x over previous
#include <cuda_runtime.h>
#include <cuda_bf16.h>
#include <math.h>

// Problem dims
#define B_   64
#define T_   256
#define U_   1024
#define G3   3072
#define M_   (B_ * T_)

// Recurrent persistent-kernel config (R2 structure)
#define GRID_R   128
#define THR_R    256
#define KSPLIT   8          // K=1024 -> 8 slices of 128
#define NSPLIT   16         // N=3072 -> 16 slices of 192
#define NCOLS    192
#define KTILE    128
#define UST      136        // smem row stride (halves)

// Big-GEMM config: CTA 128x128, BK=32, 8 warps (2m x 4n), warp tile 64x32
#define GA_ST    40         // smem row stride (halves): 32 + 8 pad
#define G_STG    20480      // halves per stage: 4 arrays x 128 rows x 40

// -------- device scratch --------------------------------------------------
__device__ float          g_xp [(size_t)M_ * G3];
__device__ unsigned short g_xhi[(size_t)M_ * U_];
__device__ unsigned short g_xlo[(size_t)M_ * U_];
__device__ unsigned short g_y1hi[(size_t)M_ * U_];
__device__ unsigned short g_y1lo[(size_t)M_ * U_];
__device__ unsigned short g_wthi[(size_t)G3 * U_];
__device__ unsigned short g_wtlo[(size_t)G3 * U_];
__device__ unsigned short g_uthi[(size_t)G3 * U_];
__device__ unsigned short g_utlo[(size_t)G3 * U_];
__device__ float          g_rp [(size_t)KSPLIT * B_ * G3];
__device__ float          g_h  [B_ * U_];
__device__ unsigned short g_hhi[B_ * U_];
__device__ unsigned short g_hlo[B_ * U_];
__device__ unsigned g_grp[8];
__device__ unsigned g_root;
__device__ unsigned g_gen;

// -------- helpers ---------------------------------------------------------
__device__ __forceinline__ void split2(float v, unsigned short& hi, unsigned short& lo) {
    __nv_bfloat16 h = __float2bfloat16(v);
    float r = v - __bfloat162float(h);
    __nv_bfloat16 l = __float2bfloat16(r);
    hi = *(unsigned short*)&h;
    lo = *(unsigned short*)&l;
}

__device__ __forceinline__ void ldsm4(unsigned (&r)[4], const void* p) {
    unsigned a = (unsigned)__cvta_generic_to_shared(p);
    asm volatile("ldmatrix.sync.aligned.m8n8.x4.shared.b16 {%0,%1,%2,%3}, [%4];"
                 : "=r"(r[0]), "=r"(r[1]), "=r"(r[2]), "=r"(r[3]) : "r"(a));
}

__device__ __forceinline__ void mma16816(float (&c)[4],
    const unsigned (&a)[4], unsigned b0, unsigned b1) {
    asm volatile(
        "mma.sync.aligned.m16n8k16.row.col.f32.bf16.bf16.f32 "
        "{%0,%1,%2,%3}, {%4,%5,%6,%7}, {%8,%9}, {%0,%1,%2,%3};"
        : "+f"(c[0]), "+f"(c[1]), "+f"(c[2]), "+f"(c[3])
        : "r"(a[0]), "r"(a[1]), "r"(a[2]), "r"(a[3]), "r"(b0), "r"(b1));
}

__device__ __forceinline__ void cp16(void* smem_dst, const void* gsrc) {
    unsigned d = (unsigned)__cvta_generic_to_shared(smem_dst);
    asm volatile("cp.async.cg.shared.global [%0], [%1], 16;" :: "r"(d), "l"(gsrc));
}

// -------- hierarchical monotonic grid barrier ------------------------------
__device__ __forceinline__ void grid_sync(int bid) {
    __syncthreads();
    if (threadIdx.x == 0) {
        __threadfence();
        unsigned gen = *(volatile unsigned*)&g_gen;
        if ((atomicAdd(&g_grp[bid & 7], 1u) & 15u) == 15u) {
            if ((atomicAdd(&g_root, 1u) & 7u) == 7u)
                atomicAdd(&g_gen, 1u);
        }
        while (*(volatile unsigned*)&g_gen == gen) { __nanosleep(32); }
        __threadfence();
    }
    __syncthreads();
}

// ---------------------------------------------------------------------------
__global__ void split_x_kernel(const float* __restrict__ x) {
    size_t n4 = (size_t)M_ * U_ / 4;
    for (size_t i = (size_t)blockIdx.x * blockDim.x + threadIdx.x; i < n4;
         i += (size_t)gridDim.x * blockDim.x) {
        float4 v = ((const float4*)x)[i];
        unsigned short h0, h1, h2, h3, l0, l1, l2, l3;
        split2(v.x, h0, l0); split2(v.y, h1, l1);
        split2(v.z, h2, l2); split2(v.w, h3, l3);
        ((ushort4*)g_xhi)[i] = make_ushort4(h0, h1, h2, h3);
        ((ushort4*)g_xlo)[i] = make_ushort4(l0, l1, l2, l3);
    }
}

__global__ void transpose_split_kernel(const float* __restrict__ Min, int dest) {
    __shared__ float tile[32][33];
    unsigned short* dh = dest ? g_uthi : g_wthi;
    unsigned short* dl = dest ? g_utlo : g_wtlo;
    int bx = blockIdx.x, by = blockIdx.y, tx = threadIdx.x;
    int x = bx * 32 + tx;
    int y0 = by * 32;
    #pragma unroll
    for (int r = threadIdx.y; r < 32; r += 8)
        tile[r][tx] = Min[(size_t)(y0 + r) * G3 + x];
    __syncthreads();
    int xo = by * 32 + tx;
    int yo0 = bx * 32;
    #pragma unroll
    for (int r = threadIdx.y; r < 32; r += 8) {
        unsigned short hi, lo;
        split2(tile[tx][r], hi, lo);
        dh[(size_t)(yo0 + r) * U_ + xo] = hi;
        dl[(size_t)(yo0 + r) * U_ + xo] = lo;
    }
}

// ---------------------------------------------------------------------------
// Big GEMM: C[M_,G3] = A@W + bias. CTA 128x128, BK=32, cp.async double-buffer.
// 8 warps 2m x 4n; warp tile 64x32 (acc=64 regs -> 2 CTAs/SM).
// ---------------------------------------------------------------------------
#define GEMM_SMEM (2 * G_STG * 2)   // 81920 bytes

__global__ __launch_bounds__(256, 2) void gemm_mma_kernel(
    const float* __restrict__ bias, int a_sel)
{
    const unsigned short* Ahg = a_sel ? g_y1hi : g_xhi;
    const unsigned short* Alg = a_sel ? g_y1lo : g_xlo;
    extern __shared__ __align__(16) unsigned short sm[];

    const int tid = threadIdx.x, w = tid >> 5, l = tid & 31;
    const int row0 = blockIdx.y * 128, col0 = blockIdx.x * 128;
    const int mb = (w >> 2) * 64, nb = (w & 3) * 32;

    const int asel = l >> 3;
    const int a_ro = ((asel & 1) << 3) + (l & 7);
    const int a_ko = (asel >> 1) << 3;
    const int b_ro = ((asel >> 1) << 3) + (l & 7);
    const int b_ko = (asel & 1) << 3;

    float acc[4][4][4];
    #pragma unroll
    for (int i = 0; i < 4; i++)
        #pragma unroll
        for (int j = 0; j < 4; j++)
            #pragma unroll
            for (int c = 0; c < 4; c++) acc[i][j][c] = 0.f;

    // 2048 16B segs per stage (4 arrays x 512), 8 per thread
    auto stage = [&](int iter) {
        int k0 = iter * 32;
        unsigned short* sb = sm + (iter & 1) * G_STG;
        #pragma unroll
        for (int q = 0; q < 8; q++) {
            int s = q * 256 + tid;
            int arr = s >> 9;                 // 0:Ah 1:Al 2:Bh 3:Bl
            int rem = s & 511;
            int r = rem >> 2, off = (rem & 3) << 3;
            const unsigned short* src =
                (arr == 0) ? Ahg : (arr == 1) ? Alg : (arr == 2) ? g_wthi : g_wtlo;
            int base_row = (arr < 2) ? row0 : col0;
            cp16(&sb[arr * 5120 + r * GA_ST + off],
                 &src[(size_t)(base_row + r) * U_ + k0 + off]);
        }
        asm volatile("cp.async.commit_group;");
    };

    stage(0);
    for (int iter = 0; iter < 32; iter++) {
        if (iter < 31) {
            stage(iter + 1);
            asm volatile("cp.async.wait_group 1;");
        } else {
            asm volatile("cp.async.wait_group 0;");
        }
        __syncthreads();
        unsigned short* sb = sm + (iter & 1) * G_STG;
        unsigned short* Ah = sb;
        unsigned short* Al = sb + 5120;
        unsigned short* Bh = sb + 10240;
        unsigned short* Bl = sb + 15360;
        #pragma unroll
        for (int kk = 0; kk < 2; kk++) {
            int kb = kk * 16;
            unsigned aH[4][4], aL[4][4];
            #pragma unroll
            for (int i = 0; i < 4; i++) {
                ldsm4(aH[i], &Ah[(mb + i * 16 + a_ro) * GA_ST + kb + a_ko]);
                ldsm4(aL[i], &Al[(mb + i * 16 + a_ro) * GA_ST + kb + a_ko]);
            }
            #pragma unroll
            for (int p = 0; p < 2; p++) {
                {
                    unsigned bH[4];
                    ldsm4(bH, &Bh[(nb + p * 16 + b_ro) * GA_ST + kb + b_ko]);
                    #pragma unroll
                    for (int i = 0; i < 4; i++) {
                        mma16816(acc[i][2 * p],     aH[i], bH[0], bH[1]);
                        mma16816(acc[i][2 * p + 1], aH[i], bH[2], bH[3]);
                    }
                    #pragma unroll
                    for (int i = 0; i < 4; i++) {
                        mma16816(acc[i][2 * p],     aL[i], bH[0], bH[1]);
                        mma16816(acc[i][2 * p + 1], aL[i], bH[2], bH[3]);
                    }
                }
                {
                    unsigned bL[4];
                    ldsm4(bL, &Bl[(nb + p * 16 + b_ro) * GA_ST + kb + b_ko]);
                    #pragma unroll
                    for (int i = 0; i < 4; i++) {
                        mma16816(acc[i][2 * p],     aH[i], bL[0], bL[1]);
                        mma16816(acc[i][2 * p + 1], aH[i], bL[2], bL[3]);
                    }
                }
            }
        }
        __syncthreads();
    }

    #pragma unroll
    for (int i = 0; i < 4; i++)
        #pragma unroll
        for (int j = 0; j < 4; j++) {
            int r = row0 + mb + i * 16 + (l >> 2);
            int c = col0 + nb + j * 8 + ((l & 3) << 1);
            float bz0 = bias[c], bz1 = bias[c + 1];
            *(float2*)&g_xp[(size_t)r * G3 + c] =
                make_float2(acc[i][j][0] + bz0, acc[i][j][1] + bz1);
            *(float2*)&g_xp[(size_t)(r + 8) * G3 + c] =
                make_float2(acc[i][j][2] + bz0, acc[i][j][3] + bz1);
        }
}

// ---------------------------------------------------------------------------
// Persistent GRU recurrence: R2 split-K structure + fast barrier + one-shot
// cp.async h staging. CTA (ks,ns): rp[64, 192] partial over K slice of 128.
// (BYTE-IDENTICAL to the R5 passing build.)
// ---------------------------------------------------------------------------
#define US_CNT   (NCOLS * UST)
#define HS_CNT   (64 * UST)
#define SMEM_DYN ((2 * US_CNT + 2 * HS_CNT) * 2)   // 139264 bytes

__global__ __launch_bounds__(THR_R, 1) void gru_recurrent_kernel(
    const float* __restrict__ bias_r,
    const float* __restrict__ h0,
    float* __restrict__ y_ext,
    int y_internal,
    float* __restrict__ state_out)
{
    extern __shared__ __align__(16) unsigned short sm[];
    unsigned short* us_hi = sm;
    unsigned short* us_lo = sm + US_CNT;
    unsigned short* hs_hi = sm + 2 * US_CNT;
    unsigned short* hs_lo = hs_hi + HS_CNT;

    const int tid = threadIdx.x, bid = blockIdx.x;
    const int w = tid >> 5, l = tid & 31;
    const int ks = bid >> 4;      // 0..7
    const int ns = bid & 15;      // 0..15

    // init hidden state (+ splits)
    for (int i = bid * THR_R + tid; i < B_ * U_; i += GRID_R * THR_R) {
        float v = h0 ? h0[i] : 0.f;
        g_h[i] = v;
        unsigned short hi, lo;
        split2(v, hi, lo);
        g_hhi[i] = hi;
        g_hlo[i] = lo;
    }

    // preload resident Ut slice: NCOLS rows x KTILE halves (hi & lo)
    for (int s = tid; s < NCOLS * (KTILE / 8); s += THR_R) {
        int row = s >> 4, k8 = (s & 15) << 3;
        size_t g = (size_t)(ns * NCOLS + row) * U_ + ks * KTILE + k8;
        *(uint4*)&us_hi[row * UST + k8] = *(const uint4*)&g_uthi[g];
        *(uint4*)&us_lo[row * UST + k8] = *(const uint4*)&g_utlo[g];
    }
    grid_sync(bid);

    const int asel = l >> 3;
    const int a_ro = ((asel & 1) << 3) + (l & 7);
    const int a_ko = (asel >> 1) << 3;
    const int b_ro = ((asel >> 1) << 3) + (l & 7);
    const int b_ko = (asel & 1) << 3;
    const int mb = (w >> 2) * 32;   // warp grid 2m x 4n, warp tile 32x48
    const int nb = (w & 3) * 48;

    // t-invariant phase-B per-thread constants
    float bz[2], br2[2], bh2[2];
    int ob[2], oj[2];
    #pragma unroll
    for (int q = 0; q < 2; q++) {
        int e = bid * THR_R + tid + q * GRID_R * THR_R;
        ob[q] = e >> 10;
        oj[q] = e & 1023;
        bz[q]  = bias_r[oj[q]];
        br2[q] = bias_r[U_ + oj[q]];
        bh2[q] = bias_r[2 * U_ + oj[q]];
    }

    for (int t = 0; t < T_; t++) {
        // ---- one-shot stage of h slice: 64 rows x 128 halves, hi+lo ----
        #pragma unroll
        for (int q = 0; q < 8; q++) {
            int seg = q * 256 + tid;          // 0..2047
            int prec = seg >> 10;
            int s = seg & 1023;
            int row = s >> 4, off = (s & 15) << 3;
            unsigned short* dst = prec ? hs_lo : hs_hi;
            const unsigned short* src = prec ? g_hlo : g_hhi;
            cp16(&dst[row * UST + off], &src[row * U_ + ks * KTILE + off]);
        }
        asm volatile("cp.async.commit_group;");
        asm volatile("cp.async.wait_group 0;");
        __syncthreads();

        // ---- Phase A: 36 MMAs x 8 k16 ----
        float acc[2][6][4];
        #pragma unroll
        for (int i = 0; i < 2; i++)
            #pragma unroll
            for (int j = 0; j < 6; j++)
                #pragma unroll
                for (int c = 0; c < 4; c++) acc[i][j][c] = 0.f;

        #pragma unroll
        for (int k16 = 0; k16 < 8; k16++) {
            int kb = k16 * 16;
            unsigned aH[2][4], aL[2][4], bH[3][4], bL[3][4];
            #pragma unroll
            for (int i = 0; i < 2; i++) {
                ldsm4(aH[i], &hs_hi[(mb + i * 16 + a_ro) * UST + kb + a_ko]);
                ldsm4(aL[i], &hs_lo[(mb + i * 16 + a_ro) * UST + kb + a_ko]);
            }
            #pragma unroll
            for (int p = 0; p < 3; p++) {
                ldsm4(bH[p], &us_hi[(nb + p * 16 + b_ro) * UST + kb + b_ko]);
                ldsm4(bL[p], &us_lo[(nb + p * 16 + b_ro) * UST + kb + b_ko]);
            }
            #pragma unroll
            for (int i = 0; i < 2; i++)
                #pragma unroll
                for (int p = 0; p < 3; p++) {
                    mma16816(acc[i][2 * p],     aH[i], bH[p][0], bH[p][1]);
                    mma16816(acc[i][2 * p + 1], aH[i], bH[p][2], bH[p][3]);
                    mma16816(acc[i][2 * p],     aH[i], bL[p][0], bL[p][1]);
                    mma16816(acc[i][2 * p + 1], aH[i], bL[p][2], bL[p][3]);
                    mma16816(acc[i][2 * p],     aL[i], bH[p][0], bH[p][1]);
                    mma16816(acc[i][2 * p + 1], aL[i], bH[p][2], bH[p][3]);
                }
        }

        // ---- store partials ----
        {
            size_t base = (size_t)ks * B_ * G3;
            #pragma unroll
            for (int i = 0; i < 2; i++)
                #pragma unroll
                for (int j = 0; j < 6; j++) {
                    int r = mb + i * 16 + (l >> 2);
                    int c = ns * NCOLS + nb + j * 8 + ((l & 3) << 1);
                    *(float2*)&g_rp[base + (size_t)r * G3 + c] =
                        make_float2(acc[i][j][0], acc[i][j][1]);
                    *(float2*)&g_rp[base + (size_t)(r + 8) * G3 + c] =
                        make_float2(acc[i][j][2], acc[i][j][3]);
                }
        }
        grid_sync(bid);

        // ---- Phase B: reduce partials, gates, h update ----
        #pragma unroll
        for (int q = 0; q < 2; q++) {
            int b = ob[q], j = oj[q];
            float rz = bz[q], rr = br2[q], rh = bh2[q];
            size_t rb = (size_t)b * G3 + j;
            #pragma unroll
            for (int p = 0; p < KSPLIT; p++) {
                size_t off = (size_t)p * B_ * G3 + rb;
                rz += __ldcg(&g_rp[off]);
                rr += __ldcg(&g_rp[off + U_]);
                rh += __ldcg(&g_rp[off + 2 * U_]);
            }
            const float* xr = &g_xp[(size_t)(b * T_ + t) * G3];
            float xz = xr[j];
            float xrr = xr[U_ + j];
            float xh = xr[2 * U_ + j];
            float z = 1.f / (1.f + expf(-(xz + rz)));
            float r = 1.f / (1.f + expf(-(xrr + rr)));
            float hh = tanhf(xh + r * rh);
            int e = b * U_ + j;
            float hnew = z * g_h[e] + (1.f - z) * hh;
            g_h[e] = hnew;
            unsigned short hi, lo;
            split2(hnew, hi, lo);
            g_hhi[e] = hi;
            g_hlo[e] = lo;
            size_t yi = (size_t)(b * T_ + t) * U_ + j;
            if (y_internal) {
                g_y1hi[yi] = hi;
                g_y1lo[yi] = lo;
            } else {
                y_ext[yi] = hnew;
            }
        }
        grid_sync(bid);
    }

    if (state_out)
        for (int i = bid * THR_R + tid; i < B_ * U_; i += GRID_R * THR_R)
            state_out[i] = __ldcg(&g_h[i]);
}

// ---------------------------------------------------------------------------
extern "C" void kernel_launch(void* const* d_in, const int* in_sizes, int n_in,
                              void* d_out, int out_size) {
    (void)in_sizes; (void)n_in; (void)out_size;
    const float* x      = (const float*)d_in[0];
    const float* hidden = (const float*)d_in[1];
    const float* W1     = (const float*)d_in[2];
    const float* U1     = (const float*)d_in[3];
    const float* b1     = (const float*)d_in[4];
    const float* W2     = (const float*)d_in[5];
    const float* U2     = (const float*)d_in[6];
    const float* b2     = (const float*)d_in[7];
    float* out   = (float*)d_out;
    float* state = out + (size_t)M_ * U_;

    cudaFuncSetAttribute(gru_recurrent_kernel,
                         cudaFuncAttributeMaxDynamicSharedMemorySize, SMEM_DYN);
    cudaFuncSetAttribute(gemm_mma_kernel,
                         cudaFuncAttributeMaxDynamicSharedMemorySize, GEMM_SMEM);

    dim3 tB(32, 8), tG(96, 32);
    dim3 gG(G3 / 128, M_ / 128);

    // ---- Layer 1 ----
    split_x_kernel<<<2048, 256>>>(x);
    transpose_split_kernel<<<tG, tB>>>(W1, 0);
    transpose_split_kernel<<<tG, tB>>>(U1, 1);
    gemm_mma_kernel<<<gG, 256, GEMM_SMEM>>>(b1, 0);
    gru_recurrent_kernel<<<GRID_R, THR_R, SMEM_DYN>>>(b1 + G3, hidden,
                                                      nullptr, 1, nullptr);
    // ---- Layer 2 ----
    transpose_split_kernel<<<tG, tB>>>(W2, 0);
    transpose_split_kernel<<<tG, tB>>>(U2, 1);
    gemm_mma_kernel<<<gG, 256, GEMM_SMEM>>>(b2, 1);
    gru_recurrent_kernel<<<GRID_R, THR_R, SMEM_DYN>>>(b2 + G3, nullptr,
                                                      out, 0, state);
}

// round 13
// speedup vs baseline: 1.0929x; 1.0028x over previous
#include <cuda_runtime.h>
#include <cuda_bf16.h>
#include <math.h>

// Problem dims
#define B_   64
#define T_   256
#define U_   1024
#define G3   3072
#define M_   (B_ * T_)

// Recurrent persistent-kernel config (R2 structure)
#define GRID_R   128
#define THR_R    256
#define KSPLIT   8          // K=1024 -> 8 slices of 128
#define NSPLIT   16         // N=3072 -> 16 slices of 192
#define NCOLS    192
#define KTILE    128
#define UST      136        // smem row stride (halves)

// Big-GEMM config: CTA 128x128, BK=32, 8 warps (2m x 4n), warp tile 64x32
#define GA_ST    40         // smem row stride (halves): 32 + 8 pad
#define G_STG    20480      // halves per stage: 4 arrays x 128 rows x 40

// -------- device scratch --------------------------------------------------
__device__ float          g_xp [(size_t)M_ * G3];
__device__ unsigned short g_xhi[(size_t)M_ * U_];
__device__ unsigned short g_xlo[(size_t)M_ * U_];
__device__ unsigned short g_y1hi[(size_t)M_ * U_];
__device__ unsigned short g_y1lo[(size_t)M_ * U_];
__device__ unsigned short g_wthi[(size_t)G3 * U_];
__device__ unsigned short g_wtlo[(size_t)G3 * U_];
__device__ unsigned short g_uthi[(size_t)G3 * U_];
__device__ unsigned short g_utlo[(size_t)G3 * U_];
__device__ float          g_rp [(size_t)KSPLIT * B_ * G3];
__device__ float          g_h  [B_ * U_];
__device__ unsigned short g_hhi[B_ * U_];
__device__ unsigned short g_hlo[B_ * U_];
__device__ unsigned g_grp[8];
__device__ unsigned g_root;
__device__ unsigned g_gen;

// -------- helpers ---------------------------------------------------------
__device__ __forceinline__ void split2(float v, unsigned short& hi, unsigned short& lo) {
    __nv_bfloat16 h = __float2bfloat16(v);
    float r = v - __bfloat162float(h);
    __nv_bfloat16 l = __float2bfloat16(r);
    hi = *(unsigned short*)&h;
    lo = *(unsigned short*)&l;
}

__device__ __forceinline__ void ldsm4(unsigned (&r)[4], const void* p) {
    unsigned a = (unsigned)__cvta_generic_to_shared(p);
    asm volatile("ldmatrix.sync.aligned.m8n8.x4.shared.b16 {%0,%1,%2,%3}, [%4];"
                 : "=r"(r[0]), "=r"(r[1]), "=r"(r[2]), "=r"(r[3]) : "r"(a));
}

__device__ __forceinline__ void mma16816(float (&c)[4],
    const unsigned (&a)[4], unsigned b0, unsigned b1) {
    asm volatile(
        "mma.sync.aligned.m16n8k16.row.col.f32.bf16.bf16.f32 "
        "{%0,%1,%2,%3}, {%4,%5,%6,%7}, {%8,%9}, {%0,%1,%2,%3};"
        : "+f"(c[0]), "+f"(c[1]), "+f"(c[2]), "+f"(c[3])
        : "r"(a[0]), "r"(a[1]), "r"(a[2]), "r"(a[3]), "r"(b0), "r"(b1));
}

__device__ __forceinline__ void cp16(void* smem_dst, const void* gsrc) {
    unsigned d = (unsigned)__cvta_generic_to_shared(smem_dst);
    asm volatile("cp.async.cg.shared.global [%0], [%1], 16;" :: "r"(d), "l"(gsrc));
}

__device__ __forceinline__ float fast_sigmoid(float s) {
    return 1.f / (1.f + __expf(-s));
}

__device__ __forceinline__ float fast_tanh(float s) {
    float r;
    asm("tanh.approx.f32 %0, %1;" : "=f"(r) : "f"(s));
    return r;
}

// -------- hierarchical monotonic grid barrier (proven R5/R8) ----------------
__device__ __forceinline__ void grid_sync(int bid) {
    __syncthreads();
    if (threadIdx.x == 0) {
        __threadfence();
        unsigned gen = *(volatile unsigned*)&g_gen;
        if ((atomicAdd(&g_grp[bid & 7], 1u) & 15u) == 15u) {
            if ((atomicAdd(&g_root, 1u) & 7u) == 7u)
                atomicAdd(&g_gen, 1u);
        }
        while (*(volatile unsigned*)&g_gen == gen) { __nanosleep(32); }
        __threadfence();
    }
    __syncthreads();
}

// ---------------------------------------------------------------------------
__global__ void split_x_kernel(const float* __restrict__ x) {
    size_t n4 = (size_t)M_ * U_ / 4;
    for (size_t i = (size_t)blockIdx.x * blockDim.x + threadIdx.x; i < n4;
         i += (size_t)gridDim.x * blockDim.x) {
        float4 v = ((const float4*)x)[i];
        unsigned short h0, h1, h2, h3, l0, l1, l2, l3;
        split2(v.x, h0, l0); split2(v.y, h1, l1);
        split2(v.z, h2, l2); split2(v.w, h3, l3);
        ((ushort4*)g_xhi)[i] = make_ushort4(h0, h1, h2, h3);
        ((ushort4*)g_xlo)[i] = make_ushort4(l0, l1, l2, l3);
    }
}

__global__ void transpose_split_kernel(const float* __restrict__ Min, int dest) {
    __shared__ float tile[32][33];
    unsigned short* dh = dest ? g_uthi : g_wthi;
    unsigned short* dl = dest ? g_utlo : g_wtlo;
    int bx = blockIdx.x, by = blockIdx.y, tx = threadIdx.x;
    int x = bx * 32 + tx;
    int y0 = by * 32;
    #pragma unroll
    for (int r = threadIdx.y; r < 32; r += 8)
        tile[r][tx] = Min[(size_t)(y0 + r) * G3 + x];
    __syncthreads();
    int xo = by * 32 + tx;
    int yo0 = bx * 32;
    #pragma unroll
    for (int r = threadIdx.y; r < 32; r += 8) {
        unsigned short hi, lo;
        split2(tile[tx][r], hi, lo);
        dh[(size_t)(yo0 + r) * U_ + xo] = hi;
        dl[(size_t)(yo0 + r) * U_ + xo] = lo;
    }
}

// ---------------------------------------------------------------------------
// Big GEMM (PROVEN R8, unchanged): CTA 128x128, BK=32, cp.async double-buffer.
// ---------------------------------------------------------------------------
#define GEMM_SMEM (2 * G_STG * 2)   // 81920 bytes

__global__ __launch_bounds__(256, 2) void gemm_mma_kernel(
    const float* __restrict__ bias, int a_sel)
{
    const unsigned short* Ahg = a_sel ? g_y1hi : g_xhi;
    const unsigned short* Alg = a_sel ? g_y1lo : g_xlo;
    extern __shared__ __align__(16) unsigned short sm[];

    const int tid = threadIdx.x, w = tid >> 5, l = tid & 31;
    const int row0 = blockIdx.y * 128, col0 = blockIdx.x * 128;
    const int mb = (w >> 2) * 64, nb = (w & 3) * 32;

    const int asel = l >> 3;
    const int a_ro = ((asel & 1) << 3) + (l & 7);
    const int a_ko = (asel >> 1) << 3;
    const int b_ro = ((asel >> 1) << 3) + (l & 7);
    const int b_ko = (asel & 1) << 3;

    float acc[4][4][4];
    #pragma unroll
    for (int i = 0; i < 4; i++)
        #pragma unroll
        for (int j = 0; j < 4; j++)
            #pragma unroll
            for (int c = 0; c < 4; c++) acc[i][j][c] = 0.f;

    auto stage = [&](int iter) {
        int k0 = iter * 32;
        unsigned short* sb = sm + (iter & 1) * G_STG;
        #pragma unroll
        for (int q = 0; q < 8; q++) {
            int s = q * 256 + tid;
            int arr = s >> 9;                 // 0:Ah 1:Al 2:Bh 3:Bl
            int rem = s & 511;
            int r = rem >> 2, off = (rem & 3) << 3;
            const unsigned short* src =
                (arr == 0) ? Ahg : (arr == 1) ? Alg : (arr == 2) ? g_wthi : g_wtlo;
            int base_row = (arr < 2) ? row0 : col0;
            cp16(&sb[arr * 5120 + r * GA_ST + off],
                 &src[(size_t)(base_row + r) * U_ + k0 + off]);
        }
        asm volatile("cp.async.commit_group;");
    };

    stage(0);
    for (int iter = 0; iter < 32; iter++) {
        if (iter < 31) {
            stage(iter + 1);
            asm volatile("cp.async.wait_group 1;");
        } else {
            asm volatile("cp.async.wait_group 0;");
        }
        __syncthreads();
        unsigned short* sb = sm + (iter & 1) * G_STG;
        unsigned short* Ah = sb;
        unsigned short* Al = sb + 5120;
        unsigned short* Bh = sb + 10240;
        unsigned short* Bl = sb + 15360;
        #pragma unroll
        for (int kk = 0; kk < 2; kk++) {
            int kb = kk * 16;
            unsigned aH[4][4], aL[4][4];
            #pragma unroll
            for (int i = 0; i < 4; i++) {
                ldsm4(aH[i], &Ah[(mb + i * 16 + a_ro) * GA_ST + kb + a_ko]);
                ldsm4(aL[i], &Al[(mb + i * 16 + a_ro) * GA_ST + kb + a_ko]);
            }
            #pragma unroll
            for (int p = 0; p < 2; p++) {
                {
                    unsigned bH[4];
                    ldsm4(bH, &Bh[(nb + p * 16 + b_ro) * GA_ST + kb + b_ko]);
                    #pragma unroll
                    for (int i = 0; i < 4; i++) {
                        mma16816(acc[i][2 * p],     aH[i], bH[0], bH[1]);
                        mma16816(acc[i][2 * p + 1], aH[i], bH[2], bH[3]);
                    }
                    #pragma unroll
                    for (int i = 0; i < 4; i++) {
                        mma16816(acc[i][2 * p],     aL[i], bH[0], bH[1]);
                        mma16816(acc[i][2 * p + 1], aL[i], bH[2], bH[3]);
                    }
                }
                {
                    unsigned bL[4];
                    ldsm4(bL, &Bl[(nb + p * 16 + b_ro) * GA_ST + kb + b_ko]);
                    #pragma unroll
                    for (int i = 0; i < 4; i++) {
                        mma16816(acc[i][2 * p],     aH[i], bL[0], bL[1]);
                        mma16816(acc[i][2 * p + 1], aH[i], bL[2], bL[3]);
                    }
                }
            }
        }
        __syncthreads();
    }

    #pragma unroll
    for (int i = 0; i < 4; i++)
        #pragma unroll
        for (int j = 0; j < 4; j++) {
            int r = row0 + mb + i * 16 + (l >> 2);
            int c = col0 + nb + j * 8 + ((l & 3) << 1);
            float bz0 = bias[c], bz1 = bias[c + 1];
            *(float2*)&g_xp[(size_t)r * G3 + c] =
                make_float2(acc[i][j][0] + bz0, acc[i][j][1] + bz1);
            *(float2*)&g_xp[(size_t)(r + 8) * G3 + c] =
                make_float2(acc[i][j][2] + bz0, acc[i][j][3] + bz1);
        }
}

// ---------------------------------------------------------------------------
// Persistent GRU recurrence: R8 structure (PROVEN). Changes vs R8:
//  - x gate inputs prefetched AFTER partial store, before barrier 1 (latency
//    hidden under the barrier wait; registers not live across the MMA phase)
//  - fast sigmoid (__expf) + tanh.approx in phase B
// ---------------------------------------------------------------------------
#define US_CNT   (NCOLS * UST)
#define HS_CNT   (64 * UST)
#define SMEM_DYN ((2 * US_CNT + 2 * HS_CNT) * 2)   // 139264 bytes

__global__ __launch_bounds__(THR_R, 1) void gru_recurrent_kernel(
    const float* __restrict__ bias_r,
    const float* __restrict__ h0,
    float* __restrict__ y_ext,
    int y_internal,
    float* __restrict__ state_out)
{
    extern __shared__ __align__(16) unsigned short sm[];
    unsigned short* us_hi = sm;
    unsigned short* us_lo = sm + US_CNT;
    unsigned short* hs_hi = sm + 2 * US_CNT;
    unsigned short* hs_lo = hs_hi + HS_CNT;

    const int tid = threadIdx.x, bid = blockIdx.x;
    const int w = tid >> 5, l = tid & 31;
    const int ks = bid >> 4;      // 0..7
    const int ns = bid & 15;      // 0..15

    // init hidden state (+ splits)
    for (int i = bid * THR_R + tid; i < B_ * U_; i += GRID_R * THR_R) {
        float v = h0 ? h0[i] : 0.f;
        g_h[i] = v;
        unsigned short hi, lo;
        split2(v, hi, lo);
        g_hhi[i] = hi;
        g_hlo[i] = lo;
    }

    // preload resident Ut slice: NCOLS rows x KTILE halves (hi & lo)
    for (int s = tid; s < NCOLS * (KTILE / 8); s += THR_R) {
        int row = s >> 4, k8 = (s & 15) << 3;
        size_t g = (size_t)(ns * NCOLS + row) * U_ + ks * KTILE + k8;
        *(uint4*)&us_hi[row * UST + k8] = *(const uint4*)&g_uthi[g];
        *(uint4*)&us_lo[row * UST + k8] = *(const uint4*)&g_utlo[g];
    }
    grid_sync(bid);

    const int asel = l >> 3;
    const int a_ro = ((asel & 1) << 3) + (l & 7);
    const int a_ko = (asel >> 1) << 3;
    const int b_ro = ((asel >> 1) << 3) + (l & 7);
    const int b_ko = (asel & 1) << 3;
    const int mb = (w >> 2) * 32;   // warp grid 2m x 4n, warp tile 32x48
    const int nb = (w & 3) * 48;

    // t-invariant phase-B per-thread constants
    float bz[2], br2[2], bh2[2];
    int ob[2], oj[2];
    #pragma unroll
    for (int q = 0; q < 2; q++) {
        int e = bid * THR_R + tid + q * GRID_R * THR_R;
        ob[q] = e >> 10;
        oj[q] = e & 1023;
        bz[q]  = bias_r[oj[q]];
        br2[q] = bias_r[U_ + oj[q]];
        bh2[q] = bias_r[2 * U_ + oj[q]];
    }

    for (int t = 0; t < T_; t++) {
        // ---- one-shot stage of h slice: 64 rows x 128 halves, hi+lo ----
        #pragma unroll
        for (int q = 0; q < 8; q++) {
            int seg = q * 256 + tid;          // 0..2047
            int prec = seg >> 10;
            int s = seg & 1023;
            int row = s >> 4, off = (s & 15) << 3;
            unsigned short* dst = prec ? hs_lo : hs_hi;
            const unsigned short* src = prec ? g_hlo : g_hhi;
            cp16(&dst[row * UST + off], &src[row * U_ + ks * KTILE + off]);
        }
        asm volatile("cp.async.commit_group;");
        asm volatile("cp.async.wait_group 0;");
        __syncthreads();

        // ---- Phase A: 36 MMAs x 8 k16 ----
        float acc[2][6][4];
        #pragma unroll
        for (int i = 0; i < 2; i++)
            #pragma unroll
            for (int j = 0; j < 6; j++)
                #pragma unroll
                for (int c = 0; c < 4; c++) acc[i][j][c] = 0.f;

        #pragma unroll
        for (int k16 = 0; k16 < 8; k16++) {
            int kb = k16 * 16;
            unsigned aH[2][4], aL[2][4], bH[3][4], bL[3][4];
            #pragma unroll
            for (int i = 0; i < 2; i++) {
                ldsm4(aH[i], &hs_hi[(mb + i * 16 + a_ro) * UST + kb + a_ko]);
                ldsm4(aL[i], &hs_lo[(mb + i * 16 + a_ro) * UST + kb + a_ko]);
            }
            #pragma unroll
            for (int p = 0; p < 3; p++) {
                ldsm4(bH[p], &us_hi[(nb + p * 16 + b_ro) * UST + kb + b_ko]);
                ldsm4(bL[p], &us_lo[(nb + p * 16 + b_ro) * UST + kb + b_ko]);
            }
            #pragma unroll
            for (int i = 0; i < 2; i++)
                #pragma unroll
                for (int p = 0; p < 3; p++) {
                    mma16816(acc[i][2 * p],     aH[i], bH[p][0], bH[p][1]);
                    mma16816(acc[i][2 * p + 1], aH[i], bH[p][2], bH[p][3]);
                    mma16816(acc[i][2 * p],     aH[i], bL[p][0], bL[p][1]);
                    mma16816(acc[i][2 * p + 1], aH[i], bL[p][2], bL[p][3]);
                    mma16816(acc[i][2 * p],     aL[i], bH[p][0], bH[p][1]);
                    mma16816(acc[i][2 * p + 1], aL[i], bH[p][2], bH[p][3]);
                }
        }

        // ---- store partials ----
        {
            size_t base = (size_t)ks * B_ * G3;
            #pragma unroll
            for (int i = 0; i < 2; i++)
                #pragma unroll
                for (int j = 0; j < 6; j++) {
                    int r = mb + i * 16 + (l >> 2);
                    int c = ns * NCOLS + nb + j * 8 + ((l & 3) << 1);
                    *(float2*)&g_rp[base + (size_t)r * G3 + c] =
                        make_float2(acc[i][j][0], acc[i][j][1]);
                    *(float2*)&g_rp[base + (size_t)(r + 8) * G3 + c] =
                        make_float2(acc[i][j][2], acc[i][j][3]);
                }
        }

        // ---- prefetch x gate inputs; latency hides under barrier 1 ----
        float xzv[2], xrv[2], xhv[2];
        #pragma unroll
        for (int q = 0; q < 2; q++) {
            const float* xr = &g_xp[(size_t)(ob[q] * T_ + t) * G3];
            xzv[q] = __ldcg(&xr[oj[q]]);
            xrv[q] = __ldcg(&xr[U_ + oj[q]]);
            xhv[q] = __ldcg(&xr[2 * U_ + oj[q]]);
        }

        grid_sync(bid);

        // ---- Phase B: reduce partials, gates, h update ----
        #pragma unroll
        for (int q = 0; q < 2; q++) {
            int b = ob[q], j = oj[q];
            float rz = bz[q], rr = br2[q], rh = bh2[q];
            size_t rb = (size_t)b * G3 + j;
            #pragma unroll
            for (int p = 0; p < KSPLIT; p++) {
                size_t off = (size_t)p * B_ * G3 + rb;
                rz += __ldcg(&g_rp[off]);
                rr += __ldcg(&g_rp[off + U_]);
                rh += __ldcg(&g_rp[off + 2 * U_]);
            }
            float z = fast_sigmoid(xzv[q] + rz);
            float r = fast_sigmoid(xrv[q] + rr);
            float hh = fast_tanh(xhv[q] + r * rh);
            int e = b * U_ + j;
            float hnew = z * g_h[e] + (1.f - z) * hh;
            g_h[e] = hnew;
            unsigned short hi, lo;
            split2(hnew, hi, lo);
            g_hhi[e] = hi;
            g_hlo[e] = lo;
            size_t yi = (size_t)(b * T_ + t) * U_ + j;
            if (y_internal) {
                g_y1hi[yi] = hi;
                g_y1lo[yi] = lo;
            } else {
                y_ext[yi] = hnew;
            }
        }
        grid_sync(bid);
    }

    if (state_out)
        for (int i = bid * THR_R + tid; i < B_ * U_; i += GRID_R * THR_R)
            state_out[i] = __ldcg(&g_h[i]);
}

// ---------------------------------------------------------------------------
extern "C" void kernel_launch(void* const* d_in, const int* in_sizes, int n_in,
                              void* d_out, int out_size) {
    (void)in_sizes; (void)n_in; (void)out_size;
    const float* x      = (const float*)d_in[0];
    const float* hidden = (const float*)d_in[1];
    const float* W1     = (const float*)d_in[2];
    const float* U1     = (const float*)d_in[3];
    const float* b1     = (const float*)d_in[4];
    const float* W2     = (const float*)d_in[5];
    const float* U2     = (const float*)d_in[6];
    const float* b2     = (const float*)d_in[7];
    float* out   = (float*)d_out;
    float* state = out + (size_t)M_ * U_;

    cudaFuncSetAttribute(gru_recurrent_kernel,
                         cudaFuncAttributeMaxDynamicSharedMemorySize, SMEM_DYN);
    cudaFuncSetAttribute(gemm_mma_kernel,
                         cudaFuncAttributeMaxDynamicSharedMemorySize, GEMM_SMEM);

    dim3 tB(32, 8), tG(96, 32);
    dim3 gG(G3 / 128, M_ / 128);

    // ---- Layer 1 ----
    split_x_kernel<<<2048, 256>>>(x);
    transpose_split_kernel<<<tG, tB>>>(W1, 0);
    transpose_split_kernel<<<tG, tB>>>(U1, 1);
    gemm_mma_kernel<<<gG, 256, GEMM_SMEM>>>(b1, 0);
    gru_recurrent_kernel<<<GRID_R, THR_R, SMEM_DYN>>>(b1 + G3, hidden,
                                                      nullptr, 1, nullptr);
    // ---- Layer 2 ----
    transpose_split_kernel<<<tG, tB>>>(W2, 0);
    transpose_split_kernel<<<tG, tB>>>(U2, 1);
    gemm_mma_kernel<<<gG, 256, GEMM_SMEM>>>(b2, 1);
    gru_recurrent_kernel<<<GRID_R, THR_R, SMEM_DYN>>>(b2 + G3, nullptr,
                                                      out, 0, state);
}